// round 11
// baseline (speedup 1.0000x reference)
#include <cuda_runtime.h>
#include <cuda_fp16.h>
#include <math.h>
#include <stdint.h>

#define BDIM 16
#define SDIM 4096
#define EDIM 512
#define HDIM 8
#define DH   64
#define TOK  (BDIM * SDIM)   // 65536 tokens
#define KDIM 512

// ---------------------------------------------------------------------------
// Scratch (allocation-free rule: device globals)
// ---------------------------------------------------------------------------
__device__ float   g_qkv[(size_t)TOK * 3 * EDIM];
__device__ __half  g_xh [(size_t)TOK * EDIM];
__device__ __half  g_oh [(size_t)TOK * EDIM];
__device__ __half  g_winh [(size_t)3 * EDIM * EDIM];
__device__ __half  g_wouth[(size_t)EDIM * EDIM];

// ---------------------------------------------------------------------------
// PTX helpers (base PTX only)
// ---------------------------------------------------------------------------
__device__ __forceinline__ uint32_t smem_u32(const void* p) {
    uint32_t a;
    asm("{ .reg .u64 t; cvta.to.shared.u64 t, %1; cvt.u32.u64 %0, t; }" : "=r"(a) : "l"(p));
    return a;
}
__device__ __forceinline__ void cpa16(uint32_t dst, const void* src) {
    asm volatile("cp.async.cg.shared.global [%0], [%1], 16;" :: "r"(dst), "l"(src));
}
#define CP_COMMIT() asm volatile("cp.async.commit_group;" ::: "memory")
#define CP_WAIT(n)  asm volatile("cp.async.wait_group %0;" :: "n"(n) : "memory")

__device__ __forceinline__ void ldsm4(uint32_t& r0, uint32_t& r1, uint32_t& r2, uint32_t& r3,
                                      uint32_t addr) {
    asm volatile("ldmatrix.sync.aligned.m8n8.x4.shared.b16 {%0,%1,%2,%3}, [%4];"
                 : "=r"(r0), "=r"(r1), "=r"(r2), "=r"(r3) : "r"(addr));
}
__device__ __forceinline__ void mma16816(float& d0, float& d1, float& d2, float& d3,
                                         uint32_t a0, uint32_t a1, uint32_t a2, uint32_t a3,
                                         uint32_t b0, uint32_t b1) {
    asm volatile(
        "mma.sync.aligned.m16n8k16.row.col.f32.f16.f16.f32 "
        "{%0,%1,%2,%3}, {%4,%5,%6,%7}, {%8,%9}, {%0,%1,%2,%3};"
        : "+f"(d0), "+f"(d1), "+f"(d2), "+f"(d3)
        : "r"(a0), "r"(a1), "r"(a2), "r"(a3), "r"(b0), "r"(b1));
}

// Swizzled smem offset within a K-major 32-col fp16 tile (row=64B, 4x16B chunks)
__device__ __forceinline__ uint32_t swz(int row, int ch) {
    return (uint32_t)(row * 64 + ((ch ^ ((row >> 1) & 3)) << 4));
}

// ---------------------------------------------------------------------------
// fp32 -> fp16 convert (vectorized)
// ---------------------------------------------------------------------------
__global__ void __launch_bounds__(256) conv_f16(
    const float4* __restrict__ x, uint2* __restrict__ h, int n4)
{
    int i = blockIdx.x * 256 + threadIdx.x;
    if (i >= n4) return;
    float4 v = x[i];
    __half2 a = __floats2half2_rn(v.x, v.y);
    __half2 b = __floats2half2_rn(v.z, v.w);
    uint2 o;
    o.x = *(uint32_t*)&a;
    o.y = *(uint32_t*)&b;
    h[i] = o;
}

// ---------------------------------------------------------------------------
// fp16 HMMA GEMM: C[M,N] = A[M,K]*B[N,K]^T + bias (fp32 out).
// 128x128 CTA tile, warp tile 64x32 (8 warps), BK=32, 16 iterations,
// 4 rotating 16KB stages, distance-3 cp.async prefetch.
// ---------------------------------------------------------------------------
#define STAGES 4
#define TILE8K 8192
#define STAGE_BYTES (2 * TILE8K)          // A 8KB | B 8KB
#define GEMM_SMEM (STAGES * STAGE_BYTES)  // 64KB
#define NCHUNK 16                         // 512 / 32

__global__ void __launch_bounds__(256, 2) gemm_hmma(
    const __half* __restrict__ A, const __half* __restrict__ B,
    const float* __restrict__ bias, float* __restrict__ C, int N)
{
    extern __shared__ char smem[];
    const uint32_t sb = smem_u32(smem);
    const int tid = threadIdx.x;
    const int wid = tid >> 5;
    const int lid = tid & 31;
    const int bm = blockIdx.y * 128;
    const int bn = blockIdx.x * 128;

    const int warp_m = (wid >> 2) * 64;   // 0 or 64
    const int warp_n = (wid & 3) * 32;    // 0,32,64,96

    // ---- load addressing: row = tid>>2 (+64), chunk = tid&3
    const int lrow0 = tid >> 2;           // 0..63
    const int lch   = tid & 3;
    const uint32_t dOff0 = swz(lrow0, lch);
    const uint32_t dOff1 = swz(lrow0 + 64, lch);
    const size_t rowd = (size_t)lrow0 * KDIM + lch * 8;

    const __half* pA = A + (size_t)bm * KDIM + rowd;
    const __half* pB = B + (size_t)bn * KDIM + rowd;

    float acc[4][4][4];
#pragma unroll
    for (int i = 0; i < 4; i++)
#pragma unroll
        for (int j = 0; j < 4; j++)
#pragma unroll
            for (int r = 0; r < 4; r++) acc[i][j][r] = 0.0f;

    // ldsm offsets (ks=0; ks=1 differs by ^32)
    uint32_t offA[4], offB[2];
#pragma unroll
    for (int fm = 0; fm < 4; fm++)
        offA[fm] = swz(warp_m + fm * 16 + (lid & 15), lid >> 4);
#pragma unroll
    for (int fb = 0; fb < 2; fb++)
        offB[fb] = swz(warp_n + fb * 16 + (lid & 15), lid >> 4);

    auto load_stage = [&](uint32_t sbase) {
        cpa16(sbase + dOff0, pA);
        cpa16(sbase + dOff1, pA + (size_t)64 * KDIM);
        cpa16(sbase + TILE8K + dOff0, pB);
        cpa16(sbase + TILE8K + dOff1, pB + (size_t)64 * KDIM);
        pA += 32;
        pB += 32;
        CP_COMMIT();
    };

    // Prolog: 3 stages in flight (distance-3)
    load_stage(sb + 0 * STAGE_BYTES);
    load_stage(sb + 1 * STAGE_BYTES);
    load_stage(sb + 2 * STAGE_BYTES);

    for (int it = 0; it < NCHUNK; it++) {
        if (it <= NCHUNK - 3)      { CP_WAIT(2); }
        else if (it == NCHUNK - 2) { CP_WAIT(1); }
        else                       { CP_WAIT(0); }
        __syncthreads();

        if (it + 3 < NCHUNK) load_stage(sb + ((it + 3) & 3) * STAGE_BYTES);

        const uint32_t sCur = sb + (it & 3) * STAGE_BYTES;

#pragma unroll
        for (int ks = 0; ks < 2; ks++) {
            const uint32_t kx = ks << 5;
            uint32_t a[4][4], b[2][4];
#pragma unroll
            for (int fm = 0; fm < 4; fm++)
                ldsm4(a[fm][0], a[fm][1], a[fm][2], a[fm][3],
                      sCur + (offA[fm] ^ kx));
#pragma unroll
            for (int fb = 0; fb < 2; fb++)
                ldsm4(b[fb][0], b[fb][1], b[fb][2], b[fb][3],
                      sCur + TILE8K + (offB[fb] ^ kx));

#pragma unroll
            for (int fm = 0; fm < 4; fm++)
#pragma unroll
                for (int fn = 0; fn < 4; fn++) {
                    const int fb = fn >> 1, hh = fn & 1;
                    mma16816(acc[fm][fn][0], acc[fm][fn][1], acc[fm][fn][2], acc[fm][fn][3],
                             a[fm][0], a[fm][1], a[fm][2], a[fm][3],
                             b[fb][hh], b[fb][hh + 2]);
                }
        }
        __syncthreads();
    }

    // ---- Epilogue: fp32 stores + bias
    const int lr = lid >> 2;
    const int lc = (lid & 3) * 2;
#pragma unroll
    for (int fm = 0; fm < 4; fm++) {
#pragma unroll
        for (int fn = 0; fn < 4; fn++) {
            const int col = bn + warp_n + fn * 8 + lc;
            const float b0 = bias[col], b1 = bias[col + 1];
            const int row0 = bm + warp_m + fm * 16 + lr;
            float2 v0 = { acc[fm][fn][0] + b0, acc[fm][fn][1] + b1 };
            float2 v1 = { acc[fm][fn][2] + b0, acc[fm][fn][3] + b1 };
            *(float2*)(C + (size_t)row0 * N + col)       = v0;
            *(float2*)(C + (size_t)(row0 + 8) * N + col) = v1;
        }
    }
}

// ---------------------------------------------------------------------------
// Attention (R9 version): one CTA per s, 256 threads, warp = head.
// fp32 qkv in, fp16 o out. One __syncthreads.
// ---------------------------------------------------------------------------
#define SPAD 514
#define ATT_SMEM ((3 * BDIM * SPAD + HDIM * BDIM * 17) * 4)

__global__ void __launch_bounds__(256, 2) attn_kernel(
    const float* __restrict__ qkv, __half* __restrict__ oh)
{
    const int s = blockIdx.x;
    extern __shared__ float sm[];
    float* q  = sm;                    // [16][SPAD]
    float* k  = q + BDIM * SPAD;
    float* v  = k + BDIM * SPAD;
    float* sc = v + BDIM * SPAD;       // [8][16][17]

    const int tid = threadIdx.x;

    // ---- coalesced load: 16 rows x 1536 contiguous floats (384 float4 each)
#pragma unroll
    for (int i = 0; i < 24; i++) {
        const int idx = tid + 256 * i;         // 0..6143
        const int b   = idx / 384;
        const int c4  = idx - b * 384;
        const int col = c4 * 4;
        float4 d = *(const float4*)(qkv + ((size_t)(b * SDIM + s)) * 1536 + col);
        float* dst;
        if (col < 512)       dst = q + b * SPAD + col;
        else if (col < 1024) dst = k + b * SPAD + (col - 512);
        else                 dst = v + b * SPAD + (col - 1024);
        dst[0] = d.x; dst[1] = d.y; dst[2] = d.z; dst[3] = d.w;
    }
    __syncthreads();

    const int w   = tid >> 5;          // head
    const int lid = tid & 31;
    const int hd  = w * DH;
    float* scw = sc + w * (BDIM * 17);

    // ---- scores
    {
        const int bq  = lid & 15;
        const int bk0 = (lid >> 4) * 8;
        float acc[8];
#pragma unroll
        for (int j = 0; j < 8; j++) acc[j] = 0.0f;
        const float* qrow = q + bq * SPAD + hd;
#pragma unroll 8
        for (int d2 = 0; d2 < 32; d2++) {
            const float2 qv = *(const float2*)(qrow + 2 * d2);
#pragma unroll
            for (int j = 0; j < 8; j++) {
                const float2 kv = *(const float2*)(k + (bk0 + j) * SPAD + hd + 2 * d2);
                acc[j] += qv.x * kv.x + qv.y * kv.y;
            }
        }
#pragma unroll
        for (int j = 0; j < 8; j++)
            scw[bq * 17 + bk0 + j] = acc[j] * 0.125f;
    }
    __syncwarp();

    // ---- softmax (lanes 0..15, one query row each)
    if (lid < 16) {
        float* row = scw + lid * 17;
        float m = -1e30f;
#pragma unroll
        for (int j = 0; j < 16; j++) m = fmaxf(m, row[j]);
        float sum = 0.0f;
        float e_[16];
#pragma unroll
        for (int j = 0; j < 16; j++) { e_[j] = expf(row[j] - m); sum += e_[j]; }
        const float inv = 1.0f / sum;
#pragma unroll
        for (int j = 0; j < 16; j++) row[j] = e_[j] * inv;
    }
    __syncwarp();

    // ---- AV + fp16 store
    {
        const int bq    = lid >> 1;
        const int dbase = (lid & 1) * 32;
        float o[32];
#pragma unroll
        for (int i = 0; i < 32; i++) o[i] = 0.0f;
#pragma unroll
        for (int bk = 0; bk < BDIM; bk++) {
            const float sv = scw[bq * 17 + bk];
            const float* vr = v + bk * SPAD + hd + dbase;
#pragma unroll
            for (int i2 = 0; i2 < 16; i2++) {
                const float2 vv = *(const float2*)(vr + 2 * i2);
                o[2 * i2]     += sv * vv.x;
                o[2 * i2 + 1] += sv * vv.y;
            }
        }
        uint32_t h2[16];
#pragma unroll
        for (int i2 = 0; i2 < 16; i2++) {
            __half2 hh = __floats2half2_rn(o[2 * i2], o[2 * i2 + 1]);
            h2[i2] = *(uint32_t*)&hh;
        }
        __half* dst = oh + ((size_t)(bq * SDIM + s)) * EDIM + hd + dbase;
#pragma unroll
        for (int c = 0; c < 4; c++) {
            uint4 pk = { h2[4 * c], h2[4 * c + 1], h2[4 * c + 2], h2[4 * c + 3] };
            *(uint4*)(dst + 8 * c) = pk;
        }
    }
}

// ---------------------------------------------------------------------------
extern "C" void kernel_launch(void* const* d_in, const int* in_sizes, int n_in,
                              void* d_out, int out_size)
{
    const float* x     = (const float*)d_in[0];
    const float* W_in  = (const float*)d_in[1];
    const float* b_in  = (const float*)d_in[2];
    const float* W_out = (const float*)d_in[3];
    const float* b_out = (const float*)d_in[4];
    float* out = (float*)d_out;

    float* qkv;
    __half *xh, *oh, *winh, *wouth;
    cudaGetSymbolAddress((void**)&qkv, g_qkv);
    cudaGetSymbolAddress((void**)&xh, g_xh);
    cudaGetSymbolAddress((void**)&oh, g_oh);
    cudaGetSymbolAddress((void**)&winh, g_winh);
    cudaGetSymbolAddress((void**)&wouth, g_wouth);

    cudaFuncSetAttribute(gemm_hmma, cudaFuncAttributeMaxDynamicSharedMemorySize, GEMM_SMEM);
    cudaFuncSetAttribute(attn_kernel, cudaFuncAttributeMaxDynamicSharedMemorySize, ATT_SMEM);

    // fp32 -> fp16 conversions
    {
        int n4 = TOK * EDIM / 4;
        conv_f16<<<(n4 + 255) / 256, 256>>>((const float4*)x, (uint2*)xh, n4);
        n4 = 3 * EDIM * EDIM / 4;
        conv_f16<<<(n4 + 255) / 256, 256>>>((const float4*)W_in, (uint2*)winh, n4);
        n4 = EDIM * EDIM / 4;
        conv_f16<<<(n4 + 255) / 256, 256>>>((const float4*)W_out, (uint2*)wouth, n4);
    }

    // 1) QKV projection -> fp32 qkv
    dim3 g1(3 * EDIM / 128, TOK / 128);
    gemm_hmma<<<g1, 256, GEMM_SMEM>>>(xh, winh, b_in, qkv, 3 * EDIM);

    // 2) Attention: one CTA per s, warp per head
    attn_kernel<<<SDIM, 256, ATT_SMEM>>>(qkv, oh);

    // 3) Output projection -> fp32 out
    dim3 g3(EDIM / 128, TOK / 128);
    gemm_hmma<<<g3, 256, GEMM_SMEM>>>(oh, wouth, b_out, out, EDIM);
}

// round 12
// speedup vs baseline: 1.6577x; 1.6577x over previous
#include <cuda_runtime.h>
#include <cuda_fp16.h>
#include <math.h>
#include <stdint.h>

#define BDIM 16
#define SDIM 4096
#define EDIM 512
#define HDIM 8
#define DH   64
#define TOK  (BDIM * SDIM)   // 65536 tokens
#define KDIM 512

// ---------------------------------------------------------------------------
// Scratch (allocation-free rule: device globals)
// ---------------------------------------------------------------------------
__device__ float   g_qkv[(size_t)TOK * 3 * EDIM];
__device__ __half  g_xh [(size_t)TOK * EDIM];
__device__ __half  g_oh [(size_t)TOK * EDIM];
__device__ __half  g_winh [(size_t)3 * EDIM * EDIM];
__device__ __half  g_wouth[(size_t)EDIM * EDIM];

// ---------------------------------------------------------------------------
// PTX helpers (base PTX only)
// ---------------------------------------------------------------------------
__device__ __forceinline__ uint32_t smem_u32(const void* p) {
    uint32_t a;
    asm("{ .reg .u64 t; cvta.to.shared.u64 t, %1; cvt.u32.u64 %0, t; }" : "=r"(a) : "l"(p));
    return a;
}
__device__ __forceinline__ void cpa16(uint32_t dst, const void* src) {
    asm volatile("cp.async.cg.shared.global [%0], [%1], 16;" :: "r"(dst), "l"(src));
}
#define CP_COMMIT() asm volatile("cp.async.commit_group;" ::: "memory")
#define CP_WAIT(n)  asm volatile("cp.async.wait_group %0;" :: "n"(n) : "memory")

__device__ __forceinline__ void ldsm4(uint32_t& r0, uint32_t& r1, uint32_t& r2, uint32_t& r3,
                                      uint32_t addr) {
    asm volatile("ldmatrix.sync.aligned.m8n8.x4.shared.b16 {%0,%1,%2,%3}, [%4];"
                 : "=r"(r0), "=r"(r1), "=r"(r2), "=r"(r3) : "r"(addr));
}
__device__ __forceinline__ void mma16816(float& d0, float& d1, float& d2, float& d3,
                                         uint32_t a0, uint32_t a1, uint32_t a2, uint32_t a3,
                                         uint32_t b0, uint32_t b1) {
    asm volatile(
        "mma.sync.aligned.m16n8k16.row.col.f32.f16.f16.f32 "
        "{%0,%1,%2,%3}, {%4,%5,%6,%7}, {%8,%9}, {%0,%1,%2,%3};"
        : "+f"(d0), "+f"(d1), "+f"(d2), "+f"(d3)
        : "r"(a0), "r"(a1), "r"(a2), "r"(a3), "r"(b0), "r"(b1));
}

// Swizzled offset in a 128-row x 64-col fp16 tile (row = 128 B = 8 x 16B chunks)
__device__ __forceinline__ uint32_t swz128(int row, int ch) {
    return (uint32_t)(row * 128 + ((ch ^ (row & 7)) << 4));
}

// ---------------------------------------------------------------------------
// fp32 -> fp16 convert (vectorized)
// ---------------------------------------------------------------------------
__global__ void __launch_bounds__(256) conv_f16(
    const float4* __restrict__ x, uint2* __restrict__ h, int n4)
{
    int i = blockIdx.x * 256 + threadIdx.x;
    if (i >= n4) return;
    float4 v = x[i];
    __half2 a = __floats2half2_rn(v.x, v.y);
    __half2 b = __floats2half2_rn(v.z, v.w);
    uint2 o;
    o.x = *(uint32_t*)&a;
    o.y = *(uint32_t*)&b;
    h[i] = o;
}

// ---------------------------------------------------------------------------
// fp16 HMMA GEMM (R9 configuration, frozen): 128x128 CTA, BK=64, 3 stages.
// ---------------------------------------------------------------------------
#define STAGES 3
#define TILE16K 16384
#define STAGE_BYTES (2 * TILE16K)
#define GEMM_SMEM (STAGES * STAGE_BYTES)
#define NCHUNK 8

__global__ void __launch_bounds__(256, 2) gemm_hmma(
    const __half* __restrict__ A, const __half* __restrict__ B,
    const float* __restrict__ bias, float* __restrict__ C, int N)
{
    extern __shared__ char smem[];
    const uint32_t sb = smem_u32(smem);
    const int tid = threadIdx.x;
    const int wid = tid >> 5;
    const int lid = tid & 31;
    const int bm = blockIdx.y * 128;
    const int bn = blockIdx.x * 128;

    const int warp_m = (wid >> 2) * 64;
    const int warp_n = (wid & 3) * 32;

    const int lrow = tid >> 3;
    const int lch  = tid & 7;
    uint32_t dOff[4];
#pragma unroll
    for (int i = 0; i < 4; i++) dOff[i] = swz128(lrow + 32 * i, lch);

    const __half* pA = A + (size_t)(bm + lrow) * KDIM + lch * 8;
    const __half* pB = B + (size_t)(bn + lrow) * KDIM + lch * 8;

    float acc[4][4][4];
#pragma unroll
    for (int i = 0; i < 4; i++)
#pragma unroll
        for (int j = 0; j < 4; j++)
#pragma unroll
            for (int r = 0; r < 4; r++) acc[i][j][r] = 0.0f;

    uint32_t offA[4], offB[2];
#pragma unroll
    for (int fm = 0; fm < 4; fm++)
        offA[fm] = swz128(warp_m + fm * 16 + (lid & 15), lid >> 4);
#pragma unroll
    for (int fb = 0; fb < 2; fb++)
        offB[fb] = swz128(warp_n + fb * 16 + (lid & 15), lid >> 4);

    auto load_stage = [&](uint32_t sbase) {
#pragma unroll
        for (int i = 0; i < 4; i++)
            cpa16(sbase + dOff[i], pA + (size_t)(32 * i) * KDIM);
#pragma unroll
        for (int i = 0; i < 4; i++)
            cpa16(sbase + TILE16K + dOff[i], pB + (size_t)(32 * i) * KDIM);
        pA += 64;
        pB += 64;
        CP_COMMIT();
    };

    uint32_t sCur = sb, sNxt = sb + STAGE_BYTES, sPrv = sb + 2 * STAGE_BYTES;

    load_stage(sCur);
    load_stage(sNxt);

    for (int it = 0; it < NCHUNK; it++) {
        if (it < NCHUNK - 1) { CP_WAIT(1); } else { CP_WAIT(0); }
        __syncthreads();

        if (it + 2 < NCHUNK) load_stage(sPrv);

#pragma unroll
        for (int kk = 0; kk < 4; kk++) {
            const uint32_t kx = (uint32_t)kk << 5;
            uint32_t a[4][4], b[2][4];
#pragma unroll
            for (int fm = 0; fm < 4; fm++)
                ldsm4(a[fm][0], a[fm][1], a[fm][2], a[fm][3],
                      sCur + (offA[fm] ^ kx));
#pragma unroll
            for (int fb = 0; fb < 2; fb++)
                ldsm4(b[fb][0], b[fb][1], b[fb][2], b[fb][3],
                      sCur + TILE16K + (offB[fb] ^ kx));

#pragma unroll
            for (int fm = 0; fm < 4; fm++)
#pragma unroll
                for (int fn = 0; fn < 4; fn++) {
                    const int fb = fn >> 1, hh = fn & 1;
                    mma16816(acc[fm][fn][0], acc[fm][fn][1], acc[fm][fn][2], acc[fm][fn][3],
                             a[fm][0], a[fm][1], a[fm][2], a[fm][3],
                             b[fb][hh], b[fb][hh + 2]);
                }
        }

        const uint32_t t = sPrv;
        sPrv = sCur; sCur = sNxt; sNxt = t;
    }

    const int lr = lid >> 2;
    const int lc = (lid & 3) * 2;
#pragma unroll
    for (int fm = 0; fm < 4; fm++) {
#pragma unroll
        for (int fn = 0; fn < 4; fn++) {
            const int col = bn + warp_n + fn * 8 + lc;
            const float b0 = bias[col], b1 = bias[col + 1];
            const int row0 = bm + warp_m + fm * 16 + lr;
            float2 v0 = { acc[fm][fn][0] + b0, acc[fm][fn][1] + b1 };
            float2 v1 = { acc[fm][fn][2] + b0, acc[fm][fn][3] + b1 };
            *(float2*)(C + (size_t)row0 * N + col)       = v0;
            *(float2*)(C + (size_t)(row0 + 8) * N + col) = v1;
        }
    }
}

// ---------------------------------------------------------------------------
// Attention: CTA = (s, head-group of 4), 128 threads, warp = head.
// smem ~54KB -> 4 CTAs/SM. fp32 qkv in, fp16 o out. One __syncthreads.
// ---------------------------------------------------------------------------
#define SPAD2 258
#define ATT_SMEM ((3 * BDIM * SPAD2 + 4 * BDIM * 17) * 4)

__global__ void __launch_bounds__(128, 4) attn_kernel(
    const float* __restrict__ qkv, __half* __restrict__ oh)
{
    const int s = blockIdx.x;
    const int g = blockIdx.y;          // head group: heads g*4 .. g*4+3
    extern __shared__ float sm[];
    float* q  = sm;                    // [16][SPAD2] (256-col slice)
    float* k  = q + BDIM * SPAD2;
    float* v  = k + BDIM * SPAD2;
    float* sc = v + BDIM * SPAD2;      // [4][16][17]

    const int tid = threadIdx.x;

    // ---- coalesced load: 3 regions x 16 rows x 256 floats (64 float4/row)
#pragma unroll
    for (int i = 0; i < 24; i++) {
        const int idx = tid + 128 * i;           // 0..3071
        const int r   = idx >> 10;               // region: 0=q 1=k 2=v
        const int rem = idx & 1023;
        const int b   = rem >> 6;
        const int col = (rem & 63) * 4;
        const float4 d = *(const float4*)(
            qkv + ((size_t)(b * SDIM + s)) * 1536 + r * 512 + g * 256 + col);
        float* dst = sm + r * (BDIM * SPAD2) + b * SPAD2 + col;
        dst[0] = d.x; dst[1] = d.y; dst[2] = d.z; dst[3] = d.w;
    }
    __syncthreads();

    const int w   = tid >> 5;          // head within group
    const int lid = tid & 31;
    const int hd  = w * DH;            // col offset within 256-slice
    float* scw = sc + w * (BDIM * 17);

    // ---- scores
    {
        const int bq  = lid & 15;
        const int bk0 = (lid >> 4) * 8;
        float acc[8];
#pragma unroll
        for (int j = 0; j < 8; j++) acc[j] = 0.0f;
        const float* qrow = q + bq * SPAD2 + hd;
#pragma unroll 8
        for (int d2 = 0; d2 < 32; d2++) {
            const float2 qv = *(const float2*)(qrow + 2 * d2);
#pragma unroll
            for (int j = 0; j < 8; j++) {
                const float2 kv = *(const float2*)(k + (bk0 + j) * SPAD2 + hd + 2 * d2);
                acc[j] += qv.x * kv.x + qv.y * kv.y;
            }
        }
#pragma unroll
        for (int j = 0; j < 8; j++)
            scw[bq * 17 + bk0 + j] = acc[j] * 0.125f;
    }
    __syncwarp();

    // ---- softmax (lanes 0..15, one query row each)
    if (lid < 16) {
        float* row = scw + lid * 17;
        float m = -1e30f;
#pragma unroll
        for (int j = 0; j < 16; j++) m = fmaxf(m, row[j]);
        float sum = 0.0f;
        float e_[16];
#pragma unroll
        for (int j = 0; j < 16; j++) { e_[j] = expf(row[j] - m); sum += e_[j]; }
        const float inv = 1.0f / sum;
#pragma unroll
        for (int j = 0; j < 16; j++) row[j] = e_[j] * inv;
    }
    __syncwarp();

    // ---- AV + fp16 store
    {
        const int bq    = lid >> 1;
        const int dbase = (lid & 1) * 32;
        float o[32];
#pragma unroll
        for (int i = 0; i < 32; i++) o[i] = 0.0f;
#pragma unroll
        for (int bk = 0; bk < BDIM; bk++) {
            const float sv = scw[bq * 17 + bk];
            const float* vr = v + bk * SPAD2 + hd + dbase;
#pragma unroll
            for (int i2 = 0; i2 < 16; i2++) {
                const float2 vv = *(const float2*)(vr + 2 * i2);
                o[2 * i2]     += sv * vv.x;
                o[2 * i2 + 1] += sv * vv.y;
            }
        }
        uint32_t h2[16];
#pragma unroll
        for (int i2 = 0; i2 < 16; i2++) {
            __half2 hh = __floats2half2_rn(o[2 * i2], o[2 * i2 + 1]);
            h2[i2] = *(uint32_t*)&hh;
        }
        __half* dst = oh + ((size_t)(bq * SDIM + s)) * EDIM + (g * 4 + w) * DH + dbase;
#pragma unroll
        for (int c = 0; c < 4; c++) {
            uint4 pk = { h2[4 * c], h2[4 * c + 1], h2[4 * c + 2], h2[4 * c + 3] };
            *(uint4*)(dst + 8 * c) = pk;
        }
    }
}

// ---------------------------------------------------------------------------
extern "C" void kernel_launch(void* const* d_in, const int* in_sizes, int n_in,
                              void* d_out, int out_size)
{
    const float* x     = (const float*)d_in[0];
    const float* W_in  = (const float*)d_in[1];
    const float* b_in  = (const float*)d_in[2];
    const float* W_out = (const float*)d_in[3];
    const float* b_out = (const float*)d_in[4];
    float* out = (float*)d_out;

    float* qkv;
    __half *xh, *oh, *winh, *wouth;
    cudaGetSymbolAddress((void**)&qkv, g_qkv);
    cudaGetSymbolAddress((void**)&xh, g_xh);
    cudaGetSymbolAddress((void**)&oh, g_oh);
    cudaGetSymbolAddress((void**)&winh, g_winh);
    cudaGetSymbolAddress((void**)&wouth, g_wouth);

    cudaFuncSetAttribute(gemm_hmma, cudaFuncAttributeMaxDynamicSharedMemorySize, GEMM_SMEM);
    cudaFuncSetAttribute(attn_kernel, cudaFuncAttributeMaxDynamicSharedMemorySize, ATT_SMEM);

    // fp32 -> fp16 conversions
    {
        int n4 = TOK * EDIM / 4;
        conv_f16<<<(n4 + 255) / 256, 256>>>((const float4*)x, (uint2*)xh, n4);
        n4 = 3 * EDIM * EDIM / 4;
        conv_f16<<<(n4 + 255) / 256, 256>>>((const float4*)W_in, (uint2*)winh, n4);
        n4 = EDIM * EDIM / 4;
        conv_f16<<<(n4 + 255) / 256, 256>>>((const float4*)W_out, (uint2*)wouth, n4);
    }

    // 1) QKV projection -> fp32 qkv
    dim3 g1(3 * EDIM / 128, TOK / 128);
    gemm_hmma<<<g1, 256, GEMM_SMEM>>>(xh, winh, b_in, qkv, 3 * EDIM);

    // 2) Attention: CTA = (s, head-group), warp per head
    dim3 g2(SDIM, HDIM / 4);
    attn_kernel<<<g2, 128, ATT_SMEM>>>(qkv, oh);

    // 3) Output projection -> fp32 out
    dim3 g3(EDIM / 128, TOK / 128);
    gemm_hmma<<<g3, 256, GEMM_SMEM>>>(oh, wouth, b_out, out, EDIM);
}